// round 14
// baseline (speedup 1.0000x reference)
#include <cuda_runtime.h>
#include <cuda_bf16.h>
#include <stdint.h>

#define NN 100000
#define EE 3200000
#define IN_CH 512
#define SCAN_T 1024

// Scratch (device globals — no allocation allowed)
__device__ int    g_degi[NN];      // edge indegree (no self-loop)
__device__ int    g_ptr[NN + 1];   // CSR row offsets (by dst)
__device__ int    g_cursor[NN];    // scatter cursors
__device__ int    g_srt[EE];       // src ids sorted by dst
__device__ float  g_dinv[NN];
__device__ float4 g_h[NN];         // hs = h_pre*dinv, then h2s = h2*dinv
__device__ float4 g_agg1[NN];
__device__ float4 g_agg2[NN];
__device__ int2   g_edge[EE];      // packed (src, dst) int32
__device__ int    g_is64;

// ---------------------------------------------------------------------------
// K1: zero indegree. Block 0 warp 0 detects edge_index dtype (int64 data ->
// all 32 sampled values in [0, NN); int32 -> fused pairs give huge values).
__global__ void k_deg_init(const void* __restrict__ ei, int n) {
    if (blockIdx.x == 0 && threadIdx.x < 32) {
        const long long* p = (const long long*)ei;
        long long v = p[threadIdx.x];
        int ok = (v >= 0 && v < NN);
        unsigned m = __ballot_sync(0xFFFFFFFFu, ok);
        if (threadIdx.x == 0) g_is64 = (m == 0xFFFFFFFFu) ? 1 : 0;
    }
    int i = blockIdx.x * blockDim.x + threadIdx.x;
    if (i < n) g_degi[i] = 0;
}

// K2: narrow edge_index to packed int2, count indegree
__global__ void k_pre(const void* __restrict__ ei, int E, int n) {
    int e = blockIdx.x * blockDim.x + threadIdx.x;
    if (e >= E) return;
    int s, d;
    if (g_is64) {
        const long long* p = (const long long*)ei;
        s = (int)p[e];
        d = (int)p[(size_t)E + e];
    } else {
        const int* p = (const int*)ei;
        s = p[e];
        d = p[E + e];
    }
    if ((unsigned)s >= (unsigned)n) s = 0;   // defensive clamp
    if ((unsigned)d >= (unsigned)n) d = 0;
    g_edge[e] = make_int2(s, d);
    atomicAdd(&g_degi[d], 1);
}

// K3: exclusive scan of g_degi -> g_ptr (and g_cursor copy). Single block.
__global__ void k_scan(int n) {
    __shared__ int part[SCAN_T];
    int tid = threadIdx.x;
    int chunk = (n + SCAN_T - 1) / SCAN_T;
    int lo = tid * chunk;
    int hi = lo + chunk; if (hi > n) hi = n;
    int s = 0;
    for (int i = lo; i < hi; i++) s += g_degi[i];
    part[tid] = s;
    __syncthreads();
    // Kogge-Stone inclusive scan over the 1024 partials
    for (int off = 1; off < SCAN_T; off <<= 1) {
        int t = (tid >= off) ? part[tid - off] : 0;
        __syncthreads();
        part[tid] += t;
        __syncthreads();
    }
    int base = part[tid] - s;                 // exclusive prefix of this chunk
    for (int i = lo; i < hi; i++) {
        g_ptr[i] = base;
        g_cursor[i] = base;
        base += g_degi[i];
    }
    if (tid == SCAN_T - 1) g_ptr[n] = base;   // == E
}

// K4: scatter src ids into dst-sorted order
__global__ void k_scatter(int E) {
    int e = blockIdx.x * blockDim.x + threadIdx.x;
    if (e >= E) return;
    int2 sd = g_edge[e];
    int pos = atomicAdd(&g_cursor[sd.y], 1);
    g_srt[pos] = sd.x;
}

// K5: h_pre = x @ W1 (warp per node, conflict-free transposed smem W).
//     dinv = rsqrt(1 + deg); store hs = h_pre * dinv.
__global__ void k_gemm(const float* __restrict__ x, const float* __restrict__ W1, int n) {
    __shared__ float sWT[4][IN_CH];   // sWT[o][k] = W1[k*4 + o]
    int tid = threadIdx.x;
    for (int i = tid; i < IN_CH * 4; i += blockDim.x) {
        int k = i >> 2, o = i & 3;
        sWT[o][k] = W1[i];
    }
    __syncthreads();

    int warp = tid >> 5, lane = tid & 31;
    int node = blockIdx.x * (blockDim.x >> 5) + warp;
    if (node >= n) return;

    const float4* xr = (const float4*)(x + (size_t)node * IN_CH);
    const float4* w0p = (const float4*)sWT[0];
    const float4* w1p = (const float4*)sWT[1];
    const float4* w2p = (const float4*)sWT[2];
    const float4* w3p = (const float4*)sWT[3];

    float4 acc = make_float4(0.f, 0.f, 0.f, 0.f);
#pragma unroll
    for (int j = 0; j < 4; j++) {
        int idx = j * 32 + lane;
        float4 xv = xr[idx];
        float4 w0 = w0p[idx], w1 = w1p[idx], w2 = w2p[idx], w3 = w3p[idx];
        acc.x += xv.x * w0.x + xv.y * w0.y + xv.z * w0.z + xv.w * w0.w;
        acc.y += xv.x * w1.x + xv.y * w1.y + xv.z * w1.z + xv.w * w1.w;
        acc.z += xv.x * w2.x + xv.y * w2.y + xv.z * w2.z + xv.w * w2.w;
        acc.w += xv.x * w3.x + xv.y * w3.y + xv.z * w3.z + xv.w * w3.w;
    }
#pragma unroll
    for (int off = 16; off; off >>= 1) {
        acc.x += __shfl_xor_sync(0xFFFFFFFFu, acc.x, off);
        acc.y += __shfl_xor_sync(0xFFFFFFFFu, acc.y, off);
        acc.z += __shfl_xor_sync(0xFFFFFFFFu, acc.z, off);
        acc.w += __shfl_xor_sync(0xFFFFFFFFu, acc.w, off);
    }
    if (lane == 0) {
        float di = rsqrtf(1.0f + (float)g_degi[node]);
        g_dinv[node] = di;
        g_h[node] = make_float4(acc.x * di, acc.y * di, acc.z * di, acc.w * di);
    }
}

// K6: agg1[node] = hs[node] + sum over CSR segment of hs[src]. Warp per node.
__global__ void k_agg1c(int n) {
    int warp = (blockIdx.x * blockDim.x + threadIdx.x) >> 5;
    int lane = threadIdx.x & 31;
    if (warp >= n) return;
    int start = g_ptr[warp], end = g_ptr[warp + 1];
    float4 s = make_float4(0.f, 0.f, 0.f, 0.f);
    for (int j = start + lane; j < end; j += 32) {
        float4 v = g_h[g_srt[j]];
        s.x += v.x; s.y += v.y; s.z += v.z; s.w += v.w;
    }
#pragma unroll
    for (int off = 16; off; off >>= 1) {
        s.x += __shfl_xor_sync(0xFFFFFFFFu, s.x, off);
        s.y += __shfl_xor_sync(0xFFFFFFFFu, s.y, off);
        s.z += __shfl_xor_sync(0xFFFFFFFFu, s.z, off);
        s.w += __shfl_xor_sync(0xFFFFFFFFu, s.w, off);
    }
    if (lane == 0) {
        float4 h = g_h[warp];   // self-loop term
        g_agg1[warp] = make_float4(s.x + h.x, s.y + h.y, s.z + h.z, s.w + h.w);
    }
}

// K7: h2 = relu(dinv*agg1 + b1); store h2s = h2*dinv
__global__ void k_relu(const float* __restrict__ b1, int n) {
    int i = blockIdx.x * blockDim.x + threadIdx.x;
    if (i >= n) return;
    float b0 = b1[0], bb1 = b1[1], b2 = b1[2], b3 = b1[3];
    float di = g_dinv[i];
    float4 a = g_agg1[i];
    float4 h;
    h.x = fmaxf(di * a.x + b0, 0.f);
    h.y = fmaxf(di * a.y + bb1, 0.f);
    h.z = fmaxf(di * a.z + b2, 0.f);
    h.w = fmaxf(di * a.w + b3, 0.f);
    g_h[i] = make_float4(h.x * di, h.y * di, h.z * di, h.w * di);
}

// K8: agg2[node] = h2s[node] + segment sum of h2s[src]
__global__ void k_agg2c(int n) {
    int warp = (blockIdx.x * blockDim.x + threadIdx.x) >> 5;
    int lane = threadIdx.x & 31;
    if (warp >= n) return;
    int start = g_ptr[warp], end = g_ptr[warp + 1];
    float4 s = make_float4(0.f, 0.f, 0.f, 0.f);
    for (int j = start + lane; j < end; j += 32) {
        float4 v = g_h[g_srt[j]];
        s.x += v.x; s.y += v.y; s.z += v.z; s.w += v.w;
    }
#pragma unroll
    for (int off = 16; off; off >>= 1) {
        s.x += __shfl_xor_sync(0xFFFFFFFFu, s.x, off);
        s.y += __shfl_xor_sync(0xFFFFFFFFu, s.y, off);
        s.z += __shfl_xor_sync(0xFFFFFFFFu, s.z, off);
        s.w += __shfl_xor_sync(0xFFFFFFFFu, s.w, off);
    }
    if (lane == 0) {
        float4 h = g_h[warp];
        g_agg2[warp] = make_float4(s.x + h.x, s.y + h.y, s.z + h.z, s.w + h.w);
    }
}

// K9: a = dinv*agg2; mu = a @ W_mu + b_mu ; logstd = a @ W_ls + b_ls
__global__ void k_final(const float* __restrict__ Wmu, const float* __restrict__ bmu,
                        const float* __restrict__ Wls, const float* __restrict__ bls,
                        float* __restrict__ out, int n) {
    int i = blockIdx.x * blockDim.x + threadIdx.x;
    if (i >= n) return;
    float di = g_dinv[i];
    float4 r = g_agg2[i];
    float4 a = make_float4(r.x * di, r.y * di, r.z * di, r.w * di);
    float m0 = a.x * Wmu[0] + a.y * Wmu[2] + a.z * Wmu[4] + a.w * Wmu[6] + bmu[0];
    float m1 = a.x * Wmu[1] + a.y * Wmu[3] + a.z * Wmu[5] + a.w * Wmu[7] + bmu[1];
    float l0 = a.x * Wls[0] + a.y * Wls[2] + a.z * Wls[4] + a.w * Wls[6] + bls[0];
    float l1 = a.x * Wls[1] + a.y * Wls[3] + a.z * Wls[5] + a.w * Wls[7] + bls[1];
    ((float2*)out)[i] = make_float2(m0, m1);
    ((float2*)(out + 2 * (size_t)n))[i] = make_float2(l0, l1);
}

extern "C" void kernel_launch(void* const* d_in, const int* in_sizes, int n_in,
                              void* d_out, int out_size) {
    const float* x   = (const float*)d_in[0];
    const void*  ei  = d_in[1];
    const float* W1  = (const float*)d_in[2];
    const float* b1  = (const float*)d_in[3];
    const float* Wmu = (const float*)d_in[4];
    const float* bmu = (const float*)d_in[5];
    const float* Wls = (const float*)d_in[6];
    const float* bls = (const float*)d_in[7];
    float* out = (float*)d_out;

    int n = in_sizes[0] / IN_CH;     // 100000
    int E = in_sizes[1] / 2;         // 3200000

    int nb_n = (n + 255) / 256;
    int nb_e = (E + 255) / 256;
    int nb_g = (n + 7) / 8;                  // warp per node, 8/block
    int nb_w = (n * 32 + 255) / 256;         // warp per node for agg

    k_deg_init<<<nb_n, 256>>>(ei, n);
    k_pre<<<nb_e, 256>>>(ei, E, n);
    k_scan<<<1, SCAN_T>>>(n);
    k_scatter<<<nb_e, 256>>>(E);
    k_gemm<<<nb_g, 256>>>(x, W1, n);
    k_agg1c<<<nb_w, 256>>>(n);
    k_relu<<<nb_n, 256>>>(b1, n);
    k_agg2c<<<nb_w, 256>>>(n);
    k_final<<<nb_n, 256>>>(Wmu, bmu, Wls, bls, out, n);
}